// round 2
// baseline (speedup 1.0000x reference)
#include <cuda_runtime.h>
#include <math.h>

#define BB 8
#define TT 4096
#define DD 512
#define UU 768
#define LL 4
#define VV 256
#define DFFC 2048
#define MM (BB*TT)          // 32768 rows
#define NSCAN 128           // persistent scan CTAs (must all be co-resident)

typedef unsigned long long ull;

// packed f32x2 helpers (SASS FFMA2 path — only reachable via PTX)
__device__ __forceinline__ void fma2(ull& acc, ull a, ull b) {
    asm("fma.rn.f32x2 %0, %1, %2, %0;" : "+l"(acc) : "l"(a), "l"(b));
}
__device__ __forceinline__ ull pk2(float lo, float hi) {
    ull r; asm("mov.b64 %0, {%1, %2};" : "=l"(r) : "f"(lo), "f"(hi)); return r;
}
__device__ __forceinline__ void upk2(float& lo, float& hi, ull p) {
    asm("mov.b64 {%0, %1}, %2;" : "=f"(lo), "=f"(hi) : "l"(p));
}

// ---------------- scratch (device globals; no cudaMalloc allowed) ----------
__device__ float g_x[MM*DD];            // residual stream (B,T,D)
__device__ float g_nrm[MM*DD];          // layernorm output
__device__ float g_xpre[4][TT*BB*UU];   // 4 gate pre-activations, (T,B,U)
__device__ float g_cfc[MM*DD];          // scan output (B,T,D)
__device__ float g_mid[MM*DFFC];        // MLP hidden
__device__ float g_h[2][BB*UU];         // recurrent state double buffer
__device__ float g_loss[2];             // {sum nll, count}
__device__ unsigned int g_bar;          // grid barrier counter (monotonic per launch)

// ---------------- embedding ------------------------------------------------
__global__ void embed_k(const int* __restrict__ idx, const float* __restrict__ wte) {
    int e = blockIdx.x*256 + threadIdx.x;        // one float4 per thread
    int row = e >> 7;                            // 128 float4 per row (D=512)
    int c = e & 127;
    int tok = idx[row];
    reinterpret_cast<float4*>(g_x)[e] =
        reinterpret_cast<const float4*>(wte)[tok*128 + c];
}

// ---------------- layernorm (one block of 128 threads per row) -------------
__global__ void ln_k(const float* __restrict__ in, const float* __restrict__ s,
                     const float* __restrict__ b, float* __restrict__ out) {
    __shared__ float red[8];
    int row = blockIdx.x;
    const float* x = in + (size_t)row*DD;
    float v[4]; float sum = 0.f, sq = 0.f;
#pragma unroll
    for (int j=0;j<4;j++) { v[j] = x[threadIdx.x + j*128]; sum += v[j]; sq += v[j]*v[j]; }
#pragma unroll
    for (int off=16; off; off>>=1) {
        sum += __shfl_xor_sync(0xffffffffu, sum, off);
        sq  += __shfl_xor_sync(0xffffffffu, sq,  off);
    }
    int w = threadIdx.x >> 5, lane = threadIdx.x & 31;
    if (lane == 0) { red[w] = sum; red[4+w] = sq; }
    __syncthreads();
    if (threadIdx.x == 0) {
        red[0] = red[0]+red[1]+red[2]+red[3];
        red[4] = red[4]+red[5]+red[6]+red[7];
    }
    __syncthreads();
    float mean = red[0]*(1.f/512.f);
    float var  = red[4]*(1.f/512.f) - mean*mean;
    float r = rsqrtf(var + 1e-5f);
#pragma unroll
    for (int j=0;j<4;j++) {
        int d = threadIdx.x + j*128;
        out[(size_t)row*DD + d] = (v[j]-mean)*r*s[d] + b[d];
    }
}

// ---------------- SGEMM 128x128x16, 8x8/thread, FFMA2 ----------------------
// EPI: 0 = C[m*N+n] = acc(+bias)        (logits)
//      1 = xpre layout (T,B,U): C[t*B*U + b*U + n] = acc + bias   (projections)
//      2 = C[m*N+n] = gelu(acc + bias)  (MLP1)
//      3 = C[m*N+n] = R[m*N+n] + acc + bias  (MLP2 + residual)
// BTR: B stored (N,K) row-major (logits: wte)
template<int EPI, bool BTR>
__global__ void __launch_bounds__(256) gemm_k(
    const float* __restrict__ A, const float* __restrict__ B,
    const float* __restrict__ bias, const float* __restrict__ R,
    float* __restrict__ C, int M, int N, int K)
{
    __shared__ float As[16][128];
    __shared__ float Bsd[16][256];   // duplicated B tile: Bsd[k][2n]=Bsd[k][2n+1]=B[k][n]
    const int tid = threadIdx.x;
    const int tx = tid & 15, ty = tid >> 4;
    const int m0 = blockIdx.y << 7, n0 = blockIdx.x << 7;

    ull acc[4][8];                   // [m-pair][n]  lo=row 2i, hi=row 2i+1
#pragma unroll
    for (int i=0;i<4;i++)
#pragma unroll
        for (int j=0;j<8;j++) acc[i][j] = 0ull;

    const int aRow = tid >> 2, aCol = tid & 3;
    const int bRow = tid >> 5, bCol = tid & 31;

    float4 pa[2], pb[2];
    // prefetch first tile into registers
#pragma unroll
    for (int h=0; h<2; h++) {
        pa[h] = *reinterpret_cast<const float4*>(&A[(size_t)(m0 + aRow + h*64)*K + aCol*4]);
        if (!BTR)
            pb[h] = *reinterpret_cast<const float4*>(&B[(size_t)(bRow + h*8)*N + n0 + bCol*4]);
        else
            pb[h] = *reinterpret_cast<const float4*>(&B[(size_t)(n0 + (tid>>2) + h*64)*K + (tid&3)*4]);
    }

    for (int k0 = 0; k0 < K; k0 += 16) {
        // stage registers -> smem
#pragma unroll
        for (int h=0; h<2; h++) {
            As[aCol*4+0][aRow+h*64] = pa[h].x;
            As[aCol*4+1][aRow+h*64] = pa[h].y;
            As[aCol*4+2][aRow+h*64] = pa[h].z;
            As[aCol*4+3][aRow+h*64] = pa[h].w;
            if (!BTR) {
                float4 d0 = make_float4(pb[h].x, pb[h].x, pb[h].y, pb[h].y);
                float4 d1 = make_float4(pb[h].z, pb[h].z, pb[h].w, pb[h].w);
                *reinterpret_cast<float4*>(&Bsd[bRow+h*8][bCol*8])   = d0;
                *reinterpret_cast<float4*>(&Bsd[bRow+h*8][bCol*8+4]) = d1;
            } else {
                int n = (tid>>2) + h*64, kc = (tid&3)*4;
                const float* pv = &pb[h].x;
#pragma unroll
                for (int q=0;q<4;q++) {
                    Bsd[kc+q][2*n]   = pv[q];
                    Bsd[kc+q][2*n+1] = pv[q];
                }
            }
        }
        __syncthreads();

        // prefetch next tile
        if (k0 + 16 < K) {
#pragma unroll
            for (int h=0; h<2; h++) {
                pa[h] = *reinterpret_cast<const float4*>(
                    &A[(size_t)(m0 + aRow + h*64)*K + k0+16 + aCol*4]);
                if (!BTR)
                    pb[h] = *reinterpret_cast<const float4*>(
                        &B[(size_t)(k0+16 + bRow + h*8)*N + n0 + bCol*4]);
                else
                    pb[h] = *reinterpret_cast<const float4*>(
                        &B[(size_t)(n0 + (tid>>2) + h*64)*K + k0+16 + (tid&3)*4]);
            }
        }

#pragma unroll
        for (int k=0;k<16;k++) {
            ulonglong2 a01 = *reinterpret_cast<const ulonglong2*>(&As[k][ty*8]);
            ulonglong2 a23 = *reinterpret_cast<const ulonglong2*>(&As[k][ty*8+4]);
            ull ra[4] = {a01.x, a01.y, a23.x, a23.y};
            ull rb[8];
#pragma unroll
            for (int q=0;q<4;q++) {
                ulonglong2 bq = *reinterpret_cast<const ulonglong2*>(&Bsd[k][tx*16 + 4*q]);
                rb[2*q]   = bq.x;
                rb[2*q+1] = bq.y;
            }
#pragma unroll
            for (int i=0;i<4;i++)
#pragma unroll
                for (int j=0;j<8;j++) fma2(acc[i][j], ra[i], rb[j]);
        }
        __syncthreads();
    }

    float bn[8];
#pragma unroll
    for (int j=0;j<8;j++) bn[j] = bias ? bias[n0 + tx*8 + j] : 0.f;

#pragma unroll
    for (int i=0;i<4;i++) {
        float lo[8], hi[8];
#pragma unroll
        for (int j=0;j<8;j++) upk2(lo[j], hi[j], acc[i][j]);
#pragma unroll
        for (int h=0;h<2;h++) {
            int m = m0 + ty*8 + 2*i + h;
            const float* vr = h ? hi : lo;
#pragma unroll
            for (int j4=0;j4<2;j4++) {
                float4 v;
                float* vv = &v.x;
#pragma unroll
                for (int j=0;j<4;j++) {
                    float t = vr[j4*4+j] + bn[j4*4+j];
                    if (EPI == 2) t = 0.5f*t*(1.f + erff(t*0.70710678118654752f));
                    vv[j] = t;
                }
                int n = n0 + tx*8 + j4*4;
                if (EPI == 1) {
                    int b_ = m >> 12, t_ = m & 4095;     // m = b*T + t, T=4096
                    *reinterpret_cast<float4*>(&C[(size_t)t_*(BB*UU) + b_*UU + n]) = v;
                } else if (EPI == 3) {
                    float4 r = *reinterpret_cast<const float4*>(&R[(size_t)m*N + n]);
                    v.x += r.x; v.y += r.y; v.z += r.z; v.w += r.w;
                    *reinterpret_cast<float4*>(&C[(size_t)m*N + n]) = v;
                } else {
                    *reinterpret_cast<float4*>(&C[(size_t)m*N + n]) = v;
                }
            }
        }
    }
}

// ---------------- persistent CfC scan (128 CTAs x 384 threads) -------------
// CTA owns 6 u-columns; warp pair (2 warps) per u, k split 384/384.
// Recurrent weights live in registers (packed f32x2) for the whole loop.
__global__ void __launch_bounds__(384, 1) scan_k(
    const float* __restrict__ Wh1, const float* __restrict__ Wh2,
    const float* __restrict__ Wha, const float* __restrict__ Whb,
    const float* __restrict__ x1,  const float* __restrict__ x2,
    const float* __restrict__ xa,  const float* __restrict__ xb)
{
    __shared__ float hs[BB*UU];          // 24KB: current h
    __shared__ float4 part[12][8][4];    // [warp][b][partial] = {s1,s2,sa,sb}
    const int tid  = threadIdx.x;
    const int w    = tid >> 5, lane = tid & 31;
    const int u    = blockIdx.x*6 + (w >> 1);
    const int kb   = (w & 1)*384 + lane*2;       // this lane's base k (pairs, stride 64)

    ull w1[6], w2[6], wa[6], wb[6];
#pragma unroll
    for (int j=0;j<6;j++) {
        int k = kb + 64*j;
        w1[j] = pk2(Wh1[(size_t)k*UU + u], Wh1[(size_t)(k+1)*UU + u]);
        w2[j] = pk2(Wh2[(size_t)k*UU + u], Wh2[(size_t)(k+1)*UU + u]);
        wa[j] = pk2(Wha[(size_t)k*UU + u], Wha[(size_t)(k+1)*UU + u]);
        wb[j] = pk2(Whb[(size_t)k*UU + u], Whb[(size_t)(k+1)*UU + u]);
    }

    const int fu  = tid / 8;                // final-stage mapping (tid<48)
    const int fB  = tid & 7;
    const int fug = blockIdx.x*6 + fu;

    for (int t = 0; t < TT; t++) {
        // prefetch this step's gate pre-activations (overlaps with h load)
        float p1=0.f, p2=0.f, pa4=0.f, pb4=0.f;
        if (tid < 48) {
            int xi = t*(BB*UU) + fB*UU + fug;
            p1 = x1[xi]; p2 = x2[xi]; pa4 = xa[xi]; pb4 = xb[xi];
        }
        // load h (L2-coherent) into smem
        if (t == 0) {
            for (int p = tid; p < BB*UU; p += 384) hs[p] = 0.f;
        } else {
            const float4* src = reinterpret_cast<const float4*>(g_h[t & 1]);
            float4* dst = reinterpret_cast<float4*>(hs);
            for (int p = tid; p < BB*UU/4; p += 384) dst[p] = __ldcg(&src[p]);
        }
        __syncthreads();

#pragma unroll
        for (int b=0;b<8;b++) {
            ull a1=0ull, a2=0ull, aa=0ull, ab=0ull;
            const float* hb = &hs[b*UU + kb];
#pragma unroll
            for (int j=0;j<6;j++) {
                ull hv = *reinterpret_cast<const ull*>(&hb[64*j]);
                fma2(a1, w1[j], hv); fma2(a2, w2[j], hv);
                fma2(aa, wa[j], hv); fma2(ab, wb[j], hv);
            }
            float l_, h_;
            upk2(l_, h_, a1); float s1 = l_ + h_;
            upk2(l_, h_, a2); float s2 = l_ + h_;
            upk2(l_, h_, aa); float sa = l_ + h_;
            upk2(l_, h_, ab); float sb = l_ + h_;
#pragma unroll
            for (int off=16; off>=4; off>>=1) {
                s1 += __shfl_xor_sync(0xffffffffu, s1, off);
                s2 += __shfl_xor_sync(0xffffffffu, s2, off);
                sa += __shfl_xor_sync(0xffffffffu, sa, off);
                sb += __shfl_xor_sync(0xffffffffu, sb, off);
            }
            if (lane < 4) part[w][b][lane] = make_float4(s1, s2, sa, sb);
        }
        __syncthreads();

        if (tid < 48) {
            float4 s = make_float4(0.f, 0.f, 0.f, 0.f);
#pragma unroll
            for (int hh=0; hh<2; hh++)
#pragma unroll
                for (int p=0; p<4; p++) {
                    float4 q = part[2*fu+hh][fB][p];
                    s.x += q.x; s.y += q.y; s.z += q.z; s.w += q.w;
                }
            float f1 = tanhf(s.x + p1), f2 = tanhf(s.y + p2);
            float ti = 1.f/(1.f + expf(-(s.z + pa4 + s.w + pb4)));
            float hn = f1 + ti*(f2 - f1);
            __stcg(&g_h[1-(t&1)][fB*UU + fug], hn);
            if (fug < DD) g_cfc[((size_t)fB*TT + t)*DD + fug] = hn;
        }
        __syncthreads();
        if (tid == 0) {                 // chip-wide barrier: monotonic counter
            __threadfence();
            atomicAdd(&g_bar, 1u);
            unsigned target = (unsigned)(t+1)*NSCAN;
            while (*reinterpret_cast<volatile unsigned*>(&g_bar) < target) {}
            __threadfence();
        }
        __syncthreads();
    }
}

// ---------------- LIF gate + residual add ----------------------------------
__global__ void lif_k(const float* __restrict__ thr_p,
                      const float* __restrict__ leak_p,
                      const float* __restrict__ steep_p) {
    int e = blockIdx.x*256 + threadIdx.x;
    int d = e & 511;
    float thr  = fabsf(thr_p[d]) * 0.1f;
    float leak = 1.f/(1.f + expf(-leak_p[d]));
    float sv = steep_p[d];
    float steep = (sv > 20.f) ? sv : log1pf(expf(sv));
    float c = g_cfc[e];
    float fire = 1.f/(1.f + expf(-steep*(fabsf(c) - thr)));
    float gate = fire + leak*(1.f - fire);
    g_x[e] += c*gate;
}

// ---------------- loss: one warp per row of 256 logits ----------------------
__global__ void loss_k(const int* __restrict__ tgt, const float* __restrict__ logits) {
    int row  = blockIdx.x*8 + (threadIdx.x >> 5);
    int lane = threadIdx.x & 31;
    const float* lr = logits + (size_t)row*VV;
    float v[8]; float mx = -3.4e38f;
#pragma unroll
    for (int j=0;j<8;j++) { v[j] = lr[lane + 32*j]; mx = fmaxf(mx, v[j]); }
#pragma unroll
    for (int off=16; off; off>>=1) mx = fmaxf(mx, __shfl_xor_sync(0xffffffffu, mx, off));
    float se = 0.f;
#pragma unroll
    for (int j=0;j<8;j++) se += expf(v[j]-mx);
#pragma unroll
    for (int off=16; off; off>>=1) se += __shfl_xor_sync(0xffffffffu, se, off);
    if (lane == 0) {
        int tv = tgt[row];
        if (tv >= 0) {
            float nll = mx + logf(se) - lr[tv];
            atomicAdd(&g_loss[0], nll);
            atomicAdd(&g_loss[1], 1.f);
        }
    }
}

__global__ void fin_k(float* __restrict__ out, int out_size) {
    if (out_size > MM*VV) out[MM*VV] = g_loss[0]/g_loss[1];
}

__global__ void zero_k() { g_bar = 0u; g_loss[0] = 0.f; g_loss[1] = 0.f; }

// ---------------- driver ----------------------------------------------------
extern "C" void kernel_launch(void* const* d_in, const int* in_sizes, int n_in,
                              void* d_out, int out_size) {
    (void)in_sizes; (void)n_in;
    const int*   idx      = (const int*)  d_in[0];
    const int*   targets  = (const int*)  d_in[1];
    const float* wte      = (const float*)d_in[2];
    const float* ln1_s    = (const float*)d_in[3];
    const float* ln1_b    = (const float*)d_in[4];
    const float* Wff1     = (const float*)d_in[5];
    const float* bff1     = (const float*)d_in[6];
    const float* Wff2     = (const float*)d_in[7];
    const float* bff2     = (const float*)d_in[8];
    const float* Wta      = (const float*)d_in[9];
    const float* bta      = (const float*)d_in[10];
    const float* Wtb      = (const float*)d_in[11];
    const float* btb      = (const float*)d_in[12];
    const float* lif_thr  = (const float*)d_in[13];
    const float* lif_leak = (const float*)d_in[14];
    const float* lif_stp  = (const float*)d_in[15];
    const float* ln2_s    = (const float*)d_in[16];
    const float* ln2_b    = (const float*)d_in[17];
    const float* mW1      = (const float*)d_in[18];
    const float* mb1      = (const float*)d_in[19];
    const float* mW2      = (const float*)d_in[20];
    const float* mb2      = (const float*)d_in[21];
    const float* lnf_s    = (const float*)d_in[22];
    const float* lnf_b    = (const float*)d_in[23];
    float* out = (float*)d_out;

    float *xp, *nm, *mid, *xpre;
    cudaGetSymbolAddress((void**)&xp,   g_x);
    cudaGetSymbolAddress((void**)&nm,   g_nrm);
    cudaGetSymbolAddress((void**)&mid,  g_mid);
    cudaGetSymbolAddress((void**)&xpre, g_xpre);

    embed_k<<<MM*DD/4/256, 256>>>(idx, wte);

    const size_t WSTRIDE = (size_t)(DD+UU)*UU;   // per-layer stride of Wff*/Wt*
    const size_t XG = (size_t)TT*BB*UU;          // per-gate xpre stride

    for (int l = 0; l < LL; l++) {
        ln_k<<<MM,128>>>(xp, ln1_s + l*DD, ln1_b + l*DD, nm);

        const float* Wg[4] = {Wff1, Wff2, Wta, Wtb};
        const float* bg[4] = {bff1, bff2, bta, btb};
        for (int g = 0; g < 4; g++) {
            gemm_k<1,false><<<dim3(UU/128, MM/128), 256>>>(
                nm, Wg[g] + (size_t)l*WSTRIDE, bg[g] + l*UU, nullptr,
                xpre + (size_t)g*XG, MM, UU, DD);
        }

        zero_k<<<1,1>>>();
        scan_k<<<NSCAN, 384>>>(
            Wff1 + (size_t)l*WSTRIDE + (size_t)DD*UU,
            Wff2 + (size_t)l*WSTRIDE + (size_t)DD*UU,
            Wta  + (size_t)l*WSTRIDE + (size_t)DD*UU,
            Wtb  + (size_t)l*WSTRIDE + (size_t)DD*UU,
            xpre, xpre + XG, xpre + 2*XG, xpre + 3*XG);

        lif_k<<<MM*DD/256, 256>>>(lif_thr + l*DD, lif_leak + l*DD, lif_stp + l*DD);

        ln_k<<<MM,128>>>(xp, ln2_s + l*DD, ln2_b + l*DD, nm);
        gemm_k<2,false><<<dim3(DFFC/128, MM/128), 256>>>(
            nm, mW1 + (size_t)l*DD*DFFC, mb1 + l*DFFC, nullptr, mid, MM, DFFC, DD);
        gemm_k<3,false><<<dim3(DD/128, MM/128), 256>>>(
            mid, mW2 + (size_t)l*DFFC*DD, mb2 + l*DD, xp, xp, MM, DD, DFFC);
    }

    ln_k<<<MM,128>>>(xp, lnf_s, lnf_b, nm);
    gemm_k<0,true><<<dim3(VV/128, MM/128), 256>>>(
        nm, wte, nullptr, nullptr, out, MM, VV, DD);
    loss_k<<<MM/8, 256>>>(targets, out);
    fin_k<<<1,1>>>(out, out_size);
}

// round 3
// speedup vs baseline: 1.6434x; 1.6434x over previous
#include <cuda_runtime.h>
#include <math.h>

#define BB 8
#define TT 4096
#define DD 512
#define UU 768
#define LL 4
#define VV 256
#define DFFC 2048
#define MM (BB*TT)          // 32768 rows
#define NSCAN 128           // persistent scan CTAs (must all be co-resident)

// ---------------- scratch (device globals; no cudaMalloc allowed) ----------
__device__ float g_x[MM*DD];            // residual stream (B,T,D)
__device__ float g_nrm[MM*DD];          // layernorm output
__device__ float g_xpre[4][TT*BB*UU];   // 4 gate pre-activations, (T,B,U)
__device__ float g_cfc[MM*DD];          // scan output (B,T,D)
__device__ float g_mid[MM*DFFC];        // MLP hidden
__device__ float g_h[2][BB*UU];         // recurrent state double buffer
__device__ float g_loss[2];             // {sum nll, count}
__device__ unsigned int g_bar;          // grid barrier counter (monotonic per launch)

// ---------------- embedding ------------------------------------------------
__global__ void embed_k(const int* __restrict__ idx, const float* __restrict__ wte) {
    int e = blockIdx.x*256 + threadIdx.x;        // one float4 per thread
    int row = e >> 7;                            // 128 float4 per row (D=512)
    int c = e & 127;
    int tok = idx[row];
    reinterpret_cast<float4*>(g_x)[e] =
        reinterpret_cast<const float4*>(wte)[tok*128 + c];
}

// ---------------- layernorm (one block of 128 threads per row) -------------
__global__ void ln_k(const float* __restrict__ in, const float* __restrict__ s,
                     const float* __restrict__ b, float* __restrict__ out) {
    __shared__ float red[8];
    int row = blockIdx.x;
    const float* x = in + (size_t)row*DD;
    float v[4]; float sum = 0.f, sq = 0.f;
#pragma unroll
    for (int j=0;j<4;j++) { v[j] = x[threadIdx.x + j*128]; sum += v[j]; sq += v[j]*v[j]; }
#pragma unroll
    for (int off=16; off; off>>=1) {
        sum += __shfl_xor_sync(0xffffffffu, sum, off);
        sq  += __shfl_xor_sync(0xffffffffu, sq,  off);
    }
    int w = threadIdx.x >> 5, lane = threadIdx.x & 31;
    if (lane == 0) { red[w] = sum; red[4+w] = sq; }
    __syncthreads();
    if (threadIdx.x == 0) {
        red[0] = red[0]+red[1]+red[2]+red[3];
        red[4] = red[4]+red[5]+red[6]+red[7];
    }
    __syncthreads();
    float mean = red[0]*(1.f/512.f);
    float var  = red[4]*(1.f/512.f) - mean*mean;
    float r = rsqrtf(var + 1e-5f);
#pragma unroll
    for (int j=0;j<4;j++) {
        int d = threadIdx.x + j*128;
        out[(size_t)row*DD + d] = (v[j]-mean)*r*s[d] + b[d];
    }
}

// ---------------- SGEMM 128x128x16, 8x8/thread (R1 verbatim) ---------------
// EPI: 0 = C[m*N+n] = acc(+bias)        (logits)
//      1 = xpre layout (T,B,U): C[t*B*U + b*U + n] = acc + bias   (projections)
//      2 = C[m*N+n] = gelu(acc + bias)  (MLP1)
//      3 = C[m*N+n] = R[m*N+n] + acc + bias  (MLP2 + residual)
// BTR: B stored (N,K) row-major (logits: wte)
template<int EPI, bool BTR>
__global__ void __launch_bounds__(256) gemm_k(
    const float* __restrict__ A, const float* __restrict__ B,
    const float* __restrict__ bias, const float* __restrict__ R,
    float* __restrict__ C, int M, int N, int K)
{
    __shared__ float As[16][128];
    __shared__ float Bs[16][128];
    const int tid = threadIdx.x;
    const int tx = tid & 15, ty = tid >> 4;
    const int m0 = blockIdx.y << 7, n0 = blockIdx.x << 7;
    float acc[8][8];
#pragma unroll
    for (int i=0;i<8;i++)
#pragma unroll
        for (int j=0;j<8;j++) acc[i][j] = 0.f;

    const int aRow = tid >> 2, aCol = tid & 3;
    const int bRow = tid >> 5, bCol = tid & 31;

    for (int k0 = 0; k0 < K; k0 += 16) {
#pragma unroll
        for (int h=0; h<2; h++) {
            float4 av = *reinterpret_cast<const float4*>(
                &A[(size_t)(m0 + aRow + h*64)*K + k0 + aCol*4]);
            As[aCol*4+0][aRow+h*64] = av.x;
            As[aCol*4+1][aRow+h*64] = av.y;
            As[aCol*4+2][aRow+h*64] = av.z;
            As[aCol*4+3][aRow+h*64] = av.w;
        }
        if (!BTR) {
#pragma unroll
            for (int h=0; h<2; h++) {
                float4 bv = *reinterpret_cast<const float4*>(
                    &B[(size_t)(k0 + bRow + h*8)*N + n0 + bCol*4]);
                *reinterpret_cast<float4*>(&Bs[bRow+h*8][bCol*4]) = bv;
            }
        } else {
#pragma unroll
            for (int h=0; h<2; h++) {
                int n = (tid>>2) + h*64, kc = (tid&3)*4;
                float4 bv = *reinterpret_cast<const float4*>(
                    &B[(size_t)(n0+n)*K + k0 + kc]);
                Bs[kc+0][n]=bv.x; Bs[kc+1][n]=bv.y; Bs[kc+2][n]=bv.z; Bs[kc+3][n]=bv.w;
            }
        }
        __syncthreads();
#pragma unroll
        for (int k=0;k<16;k++) {
            float ra[8], rb[8];
            *reinterpret_cast<float4*>(ra)   = *reinterpret_cast<const float4*>(&As[k][ty*8]);
            *reinterpret_cast<float4*>(ra+4) = *reinterpret_cast<const float4*>(&As[k][ty*8+4]);
            *reinterpret_cast<float4*>(rb)   = *reinterpret_cast<const float4*>(&Bs[k][tx*8]);
            *reinterpret_cast<float4*>(rb+4) = *reinterpret_cast<const float4*>(&Bs[k][tx*8+4]);
#pragma unroll
            for (int i=0;i<8;i++)
#pragma unroll
                for (int j=0;j<8;j++) acc[i][j] = fmaf(ra[i], rb[j], acc[i][j]);
        }
        __syncthreads();
    }

    float bn[8];
#pragma unroll
    for (int j=0;j<8;j++) bn[j] = bias ? bias[n0 + tx*8 + j] : 0.f;

#pragma unroll
    for (int i=0;i<8;i++) {
        int m = m0 + ty*8 + i;
#pragma unroll
        for (int j4=0;j4<2;j4++) {
            float4 v;
            float* vv = &v.x;
#pragma unroll
            for (int j=0;j<4;j++) {
                float t = acc[i][j4*4+j] + bn[j4*4+j];
                if (EPI == 2) t = 0.5f*t*(1.f + erff(t*0.70710678118654752f));
                vv[j] = t;
            }
            int n = n0 + tx*8 + j4*4;
            if (EPI == 1) {
                int b_ = m >> 12, t_ = m & 4095;     // m = b*T + t, T=4096
                *reinterpret_cast<float4*>(&C[(size_t)t_*(BB*UU) + b_*UU + n]) = v;
            } else if (EPI == 3) {
                float4 r = *reinterpret_cast<const float4*>(&R[(size_t)m*N + n]);
                v.x += r.x; v.y += r.y; v.z += r.z; v.w += r.w;
                *reinterpret_cast<float4*>(&C[(size_t)m*N + n]) = v;
            } else {
                *reinterpret_cast<float4*>(&C[(size_t)m*N + n]) = v;
            }
        }
    }
}

// ---------------- persistent CfC scan (128 CTAs x 384 threads) -------------
// CTA owns 6 u-columns. Warp w: u = w>>1, batches bh..bh+3 (bh = (w&1)*4).
// Full-warp 32-way k-split per dot; lane l owns k = {q*128 + l*4 .. +3}, q<6.
// float4 smem loads (16B/lane contiguous => conflict-free), float4 gate accs,
// 3-level shfl reduction, packed STS.128 partials, 48-thread finalize.
__global__ void __launch_bounds__(384, 1) scan_k(
    const float* __restrict__ Wh1, const float* __restrict__ Wh2,
    const float* __restrict__ Wha, const float* __restrict__ Whb,
    const float* __restrict__ x1,  const float* __restrict__ x2,
    const float* __restrict__ xa,  const float* __restrict__ xb)
{
    __shared__ float hs[BB*UU];            // 24KB current h
    __shared__ float4 part[12][4][4];      // [warp][b-local][quarter-partial]
    const int tid  = threadIdx.x;
    const int w    = tid >> 5, lane = tid & 31;
    const int u    = blockIdx.x*6 + (w >> 1);
    const int bh   = (w & 1) * 4;

    // weight registers: per gate, 6 float4 chunks (k = q*128 + lane*4 + e)
    float4 w1[6], w2[6], wa[6], wb[6];
#pragma unroll
    for (int q=0;q<6;q++) {
        float* p1_ = reinterpret_cast<float*>(&w1[q]);
        float* p2_ = reinterpret_cast<float*>(&w2[q]);
        float* pa_ = reinterpret_cast<float*>(&wa[q]);
        float* pb_ = reinterpret_cast<float*>(&wb[q]);
#pragma unroll
        for (int e=0;e<4;e++) {
            size_t k = (size_t)(q*128 + lane*4 + e);
            p1_[e] = Wh1[k*UU + u];
            p2_[e] = Wh2[k*UU + u];
            pa_[e] = Wha[k*UU + u];
            pb_[e] = Whb[k*UU + u];
        }
    }

    // finalize-stage mapping (tid < 48): one (b, u-local) pair each
    const int fu  = tid / 8;
    const int fB  = tid & 7;
    const int fug = blockIdx.x*6 + fu;
    const int fw  = 2*fu + (fB >> 2);
    const int fbl = fB & 3;

    // prefetch xpre for t=0
    float p1=0.f, p2=0.f, pa4=0.f, pb4=0.f;
    if (tid < 48) {
        int xi = fB*UU + fug;
        p1 = x1[xi]; p2 = x2[xi]; pa4 = xa[xi]; pb4 = xb[xi];
    }

    for (int t = 0; t < TT; t++) {
        // stage h into smem
        if (t == 0) {
            for (int p = tid; p < BB*UU; p += 384) hs[p] = 0.f;
        } else {
            const float4* src = reinterpret_cast<const float4*>(g_h[t & 1]);
            float4* dst = reinterpret_cast<float4*>(hs);
#pragma unroll
            for (int p = 0; p < 4; p++) dst[tid + 384*p] = __ldcg(&src[tid + 384*p]);
        }
        __syncthreads();

#pragma unroll
        for (int bl=0; bl<4; bl++) {
            const int b = bh + bl;
            const float4* hp = reinterpret_cast<const float4*>(&hs[b*UU]);
            float4 a1 = make_float4(0.f,0.f,0.f,0.f);
            float4 a2 = a1, aa = a1, ab = a1;
#pragma unroll
            for (int q=0;q<6;q++) {
                float4 hv = hp[q*32 + lane];
                a1.x = fmaf(w1[q].x, hv.x, a1.x); a1.y = fmaf(w1[q].y, hv.y, a1.y);
                a1.z = fmaf(w1[q].z, hv.z, a1.z); a1.w = fmaf(w1[q].w, hv.w, a1.w);
                a2.x = fmaf(w2[q].x, hv.x, a2.x); a2.y = fmaf(w2[q].y, hv.y, a2.y);
                a2.z = fmaf(w2[q].z, hv.z, a2.z); a2.w = fmaf(w2[q].w, hv.w, a2.w);
                aa.x = fmaf(wa[q].x, hv.x, aa.x); aa.y = fmaf(wa[q].y, hv.y, aa.y);
                aa.z = fmaf(wa[q].z, hv.z, aa.z); aa.w = fmaf(wa[q].w, hv.w, aa.w);
                ab.x = fmaf(wb[q].x, hv.x, ab.x); ab.y = fmaf(wb[q].y, hv.y, ab.y);
                ab.z = fmaf(wb[q].z, hv.z, ab.z); ab.w = fmaf(wb[q].w, hv.w, ab.w);
            }
            float s1 = (a1.x+a1.y)+(a1.z+a1.w);
            float s2 = (a2.x+a2.y)+(a2.z+a2.w);
            float sa = (aa.x+aa.y)+(aa.z+aa.w);
            float sb = (ab.x+ab.y)+(ab.z+ab.w);
#pragma unroll
            for (int off=16; off>=4; off>>=1) {
                s1 += __shfl_xor_sync(0xffffffffu, s1, off);
                s2 += __shfl_xor_sync(0xffffffffu, s2, off);
                sa += __shfl_xor_sync(0xffffffffu, sa, off);
                sb += __shfl_xor_sync(0xffffffffu, sb, off);
            }
            if (lane < 4) part[w][bl][lane] = make_float4(s1, s2, sa, sb);
        }
        __syncthreads();

        if (tid < 48) {
            float4 q0 = part[fw][fbl][0], q1 = part[fw][fbl][1];
            float4 q2 = part[fw][fbl][2], q3 = part[fw][fbl][3];
            float s1 = (q0.x+q1.x)+(q2.x+q3.x) + p1;
            float s2 = (q0.y+q1.y)+(q2.y+q3.y) + p2;
            float sa = (q0.z+q1.z)+(q2.z+q3.z) + pa4;
            float sb = (q0.w+q1.w)+(q2.w+q3.w) + pb4;
            float f1 = tanhf(s1), f2 = tanhf(s2);
            float ti = 1.f/(1.f + expf(-(sa+sb)));
            float hn = f1 + ti*(f2 - f1);
            __stcg(&g_h[1-(t&1)][fB*UU + fug], hn);
            if (fug < DD) g_cfc[((size_t)fB*TT + t)*DD + fug] = hn;
            // prefetch next step's xpre while others spin at the barrier
            if (t+1 < TT) {
                int xi = (t+1)*(BB*UU) + fB*UU + fug;
                p1 = x1[xi]; p2 = x2[xi]; pa4 = xa[xi]; pb4 = xb[xi];
            }
        }
        __syncthreads();
        if (tid == 0) {                 // chip-wide barrier: monotonic counter
            __threadfence();
            atomicAdd(&g_bar, 1u);
            unsigned target = (unsigned)(t+1)*NSCAN;
            while (*reinterpret_cast<volatile unsigned*>(&g_bar) < target) {}
            __threadfence();
        }
        __syncthreads();
    }
}

// ---------------- LIF gate + residual add ----------------------------------
__global__ void lif_k(const float* __restrict__ thr_p,
                      const float* __restrict__ leak_p,
                      const float* __restrict__ steep_p) {
    int e = blockIdx.x*256 + threadIdx.x;
    int d = e & 511;
    float thr  = fabsf(thr_p[d]) * 0.1f;
    float leak = 1.f/(1.f + expf(-leak_p[d]));
    float sv = steep_p[d];
    float steep = (sv > 20.f) ? sv : log1pf(expf(sv));
    float c = g_cfc[e];
    float fire = 1.f/(1.f + expf(-steep*(fabsf(c) - thr)));
    float gate = fire + leak*(1.f - fire);
    g_x[e] += c*gate;
}

// ---------------- loss: one warp per row of 256 logits ----------------------
__global__ void loss_k(const int* __restrict__ tgt, const float* __restrict__ logits) {
    int row  = blockIdx.x*8 + (threadIdx.x >> 5);
    int lane = threadIdx.x & 31;
    const float* lr = logits + (size_t)row*VV;
    float v[8]; float mx = -3.4e38f;
#pragma unroll
    for (int j=0;j<8;j++) { v[j] = lr[lane + 32*j]; mx = fmaxf(mx, v[j]); }
#pragma unroll
    for (int off=16; off; off>>=1) mx = fmaxf(mx, __shfl_xor_sync(0xffffffffu, mx, off));
    float se = 0.f;
#pragma unroll
    for (int j=0;j<8;j++) se += expf(v[j]-mx);
#pragma unroll
    for (int off=16; off; off>>=1) se += __shfl_xor_sync(0xffffffffu, se, off);
    if (lane == 0) {
        int tv = tgt[row];
        if (tv >= 0) {
            float nll = mx + logf(se) - lr[tv];
            atomicAdd(&g_loss[0], nll);
            atomicAdd(&g_loss[1], 1.f);
        }
    }
}

__global__ void fin_k(float* __restrict__ out, int out_size) {
    if (out_size > MM*VV) out[MM*VV] = g_loss[0]/g_loss[1];
}

__global__ void zero_k() { g_bar = 0u; g_loss[0] = 0.f; g_loss[1] = 0.f; }

// ---------------- driver ----------------------------------------------------
extern "C" void kernel_launch(void* const* d_in, const int* in_sizes, int n_in,
                              void* d_out, int out_size) {
    (void)in_sizes; (void)n_in;
    const int*   idx      = (const int*)  d_in[0];
    const int*   targets  = (const int*)  d_in[1];
    const float* wte      = (const float*)d_in[2];
    const float* ln1_s    = (const float*)d_in[3];
    const float* ln1_b    = (const float*)d_in[4];
    const float* Wff1     = (const float*)d_in[5];
    const float* bff1     = (const float*)d_in[6];
    const float* Wff2     = (const float*)d_in[7];
    const float* bff2     = (const float*)d_in[8];
    const float* Wta      = (const float*)d_in[9];
    const float* bta      = (const float*)d_in[10];
    const float* Wtb      = (const float*)d_in[11];
    const float* btb      = (const float*)d_in[12];
    const float* lif_thr  = (const float*)d_in[13];
    const float* lif_leak = (const float*)d_in[14];
    const float* lif_stp  = (const float*)d_in[15];
    const float* ln2_s    = (const float*)d_in[16];
    const float* ln2_b    = (const float*)d_in[17];
    const float* mW1      = (const float*)d_in[18];
    const float* mb1      = (const float*)d_in[19];
    const float* mW2      = (const float*)d_in[20];
    const float* mb2      = (const float*)d_in[21];
    const float* lnf_s    = (const float*)d_in[22];
    const float* lnf_b    = (const float*)d_in[23];
    float* out = (float*)d_out;

    float *xp, *nm, *mid, *xpre;
    cudaGetSymbolAddress((void**)&xp,   g_x);
    cudaGetSymbolAddress((void**)&nm,   g_nrm);
    cudaGetSymbolAddress((void**)&mid,  g_mid);
    cudaGetSymbolAddress((void**)&xpre, g_xpre);

    embed_k<<<MM*DD/4/256, 256>>>(idx, wte);

    const size_t WSTRIDE = (size_t)(DD+UU)*UU;   // per-layer stride of Wff*/Wt*
    const size_t XG = (size_t)TT*BB*UU;          // per-gate xpre stride

    for (int l = 0; l < LL; l++) {
        ln_k<<<MM,128>>>(xp, ln1_s + l*DD, ln1_b + l*DD, nm);

        const float* Wg[4] = {Wff1, Wff2, Wta, Wtb};
        const float* bg[4] = {bff1, bff2, bta, btb};
        for (int g = 0; g < 4; g++) {
            gemm_k<1,false><<<dim3(UU/128, MM/128), 256>>>(
                nm, Wg[g] + (size_t)l*WSTRIDE, bg[g] + l*UU, nullptr,
                xpre + (size_t)g*XG, MM, UU, DD);
        }

        zero_k<<<1,1>>>();
        scan_k<<<NSCAN, 384>>>(
            Wff1 + (size_t)l*WSTRIDE + (size_t)DD*UU,
            Wff2 + (size_t)l*WSTRIDE + (size_t)DD*UU,
            Wta  + (size_t)l*WSTRIDE + (size_t)DD*UU,
            Wtb  + (size_t)l*WSTRIDE + (size_t)DD*UU,
            xpre, xpre + XG, xpre + 2*XG, xpre + 3*XG);

        lif_k<<<MM*DD/256, 256>>>(lif_thr + l*DD, lif_leak + l*DD, lif_stp + l*DD);

        ln_k<<<MM,128>>>(xp, ln2_s + l*DD, ln2_b + l*DD, nm);
        gemm_k<2,false><<<dim3(DFFC/128, MM/128), 256>>>(
            nm, mW1 + (size_t)l*DD*DFFC, mb1 + l*DFFC, nullptr, mid, MM, DFFC, DD);
        gemm_k<3,false><<<dim3(DD/128, MM/128), 256>>>(
            mid, mW2 + (size_t)l*DFFC*DD, mb2 + l*DD, xp, xp, MM, DD, DFFC);
    }

    ln_k<<<MM,128>>>(xp, lnf_s, lnf_b, nm);
    gemm_k<0,true><<<dim3(VV/128, MM/128), 256>>>(
        nm, wte, nullptr, nullptr, out, MM, VV, DD);
    loss_k<<<MM/8, 256>>>(targets, out);
    fin_k<<<1,1>>>(out, out_size);
}

// round 4
// speedup vs baseline: 1.7173x; 1.0450x over previous
#include <cuda_runtime.h>
#include <math.h>

#define BB 8
#define TT 4096
#define DD 512
#define UU 768
#define LL 4
#define VV 256
#define DFFC 2048
#define MM (BB*TT)          // 32768 rows
#define NSCAN 128           // persistent scan CTAs (must all be co-resident)

typedef unsigned long long ull;

// packed f32x2 helpers (SASS FFMA2 path — only reachable via PTX)
__device__ __forceinline__ void fma2(ull& acc, ull a, ull b) {
    asm("fma.rn.f32x2 %0, %1, %2, %0;" : "+l"(acc) : "l"(a), "l"(b));
}
__device__ __forceinline__ ull pk2(float lo, float hi) {
    ull r; asm("mov.b64 %0, {%1, %2};" : "=l"(r) : "f"(lo), "f"(hi)); return r;
}
__device__ __forceinline__ void upk2(float& lo, float& hi, ull p) {
    asm("mov.b64 {%0, %1}, %2;" : "=f"(lo), "=f"(hi) : "l"(p));
}
__device__ __forceinline__ void bar_red_release(unsigned* p) {
    asm volatile("red.release.gpu.add.u32 [%0], 1;" :: "l"(p) : "memory");
}
__device__ __forceinline__ unsigned ld_acquire(const unsigned* p) {
    unsigned v;
    asm volatile("ld.acquire.gpu.u32 %0, [%1];" : "=r"(v) : "l"(p) : "memory");
    return v;
}

// ---------------- scratch (device globals; no cudaMalloc allowed) ----------
__device__ float g_x[MM*DD];            // residual stream (B,T,D)
__device__ float g_nrm[MM*DD];          // layernorm output
__device__ float g_xpre[4][TT*BB*UU];   // 4 gate pre-activations, (T,B,U)
__device__ float g_cfc[MM*DD];          // scan output (B,T,D)
__device__ float g_mid[MM*DFFC];        // MLP hidden
__device__ float g_h[2][BB*UU];         // recurrent state double buffer
__device__ float g_loss[2];             // {sum nll, count}
__device__ unsigned int g_bar;          // grid barrier counter (monotonic per launch)

// ---------------- embedding ------------------------------------------------
__global__ void embed_k(const int* __restrict__ idx, const float* __restrict__ wte) {
    int e = blockIdx.x*256 + threadIdx.x;        // one float4 per thread
    int row = e >> 7;                            // 128 float4 per row (D=512)
    int c = e & 127;
    int tok = idx[row];
    reinterpret_cast<float4*>(g_x)[e] =
        reinterpret_cast<const float4*>(wte)[tok*128 + c];
}

// ---------------- layernorm (one block of 128 threads per row) -------------
__global__ void ln_k(const float* __restrict__ in, const float* __restrict__ s,
                     const float* __restrict__ b, float* __restrict__ out) {
    __shared__ float red[8];
    int row = blockIdx.x;
    const float* x = in + (size_t)row*DD;
    float v[4]; float sum = 0.f, sq = 0.f;
#pragma unroll
    for (int j=0;j<4;j++) { v[j] = x[threadIdx.x + j*128]; sum += v[j]; sq += v[j]*v[j]; }
#pragma unroll
    for (int off=16; off; off>>=1) {
        sum += __shfl_xor_sync(0xffffffffu, sum, off);
        sq  += __shfl_xor_sync(0xffffffffu, sq,  off);
    }
    int w = threadIdx.x >> 5, lane = threadIdx.x & 31;
    if (lane == 0) { red[w] = sum; red[4+w] = sq; }
    __syncthreads();
    if (threadIdx.x == 0) {
        red[0] = red[0]+red[1]+red[2]+red[3];
        red[4] = red[4]+red[5]+red[6]+red[7];
    }
    __syncthreads();
    float mean = red[0]*(1.f/512.f);
    float var  = red[4]*(1.f/512.f) - mean*mean;
    float r = rsqrtf(var + 1e-5f);
#pragma unroll
    for (int j=0;j<4;j++) {
        int d = threadIdx.x + j*128;
        out[(size_t)row*DD + d] = (v[j]-mean)*r*s[d] + b[d];
    }
}

// ---------------- SGEMM 128x128x16, 8x8/thread -----------------------------
// EPI: 0 = C[m*N+n] = acc(+bias)        (logits)
//      1 = xpre layout (T,B,U): C[t*B*U + b*U + n] = acc + bias   (projections)
//      2 = C[m*N+n] = gelu(acc + bias)  (MLP1)
//      3 = C[m*N+n] = R[m*N+n] + acc + bias  (MLP2 + residual)
// BTR: B stored (N,K) row-major (logits: wte)
template<int EPI, bool BTR>
__global__ void __launch_bounds__(256, 2) gemm_k(
    const float* __restrict__ A, const float* __restrict__ B,
    const float* __restrict__ bias, const float* __restrict__ R,
    float* __restrict__ C, int M, int N, int K)
{
    __shared__ float As[16][128];
    __shared__ float Bs[16][128];
    const int tid = threadIdx.x;
    const int tx = tid & 15, ty = tid >> 4;
    const int m0 = blockIdx.y << 7, n0 = blockIdx.x << 7;
    float acc[8][8];
#pragma unroll
    for (int i=0;i<8;i++)
#pragma unroll
        for (int j=0;j<8;j++) acc[i][j] = 0.f;

    const int aRow = tid >> 2, aCol = tid & 3;
    const int bRow = tid >> 5, bCol = tid & 31;

    for (int k0 = 0; k0 < K; k0 += 16) {
#pragma unroll
        for (int h=0; h<2; h++) {
            float4 av = *reinterpret_cast<const float4*>(
                &A[(size_t)(m0 + aRow + h*64)*K + k0 + aCol*4]);
            As[aCol*4+0][aRow+h*64] = av.x;
            As[aCol*4+1][aRow+h*64] = av.y;
            As[aCol*4+2][aRow+h*64] = av.z;
            As[aCol*4+3][aRow+h*64] = av.w;
        }
        if (!BTR) {
#pragma unroll
            for (int h=0; h<2; h++) {
                float4 bv = *reinterpret_cast<const float4*>(
                    &B[(size_t)(k0 + bRow + h*8)*N + n0 + bCol*4]);
                *reinterpret_cast<float4*>(&Bs[bRow+h*8][bCol*4]) = bv;
            }
        } else {
#pragma unroll
            for (int h=0; h<2; h++) {
                int n = (tid>>2) + h*64, kc = (tid&3)*4;
                float4 bv = *reinterpret_cast<const float4*>(
                    &B[(size_t)(n0+n)*K + k0 + kc]);
                Bs[kc+0][n]=bv.x; Bs[kc+1][n]=bv.y; Bs[kc+2][n]=bv.z; Bs[kc+3][n]=bv.w;
            }
        }
        __syncthreads();
#pragma unroll
        for (int k=0;k<16;k++) {
            float ra[8], rb[8];
            *reinterpret_cast<float4*>(ra)   = *reinterpret_cast<const float4*>(&As[k][ty*8]);
            *reinterpret_cast<float4*>(ra+4) = *reinterpret_cast<const float4*>(&As[k][ty*8+4]);
            *reinterpret_cast<float4*>(rb)   = *reinterpret_cast<const float4*>(&Bs[k][tx*8]);
            *reinterpret_cast<float4*>(rb+4) = *reinterpret_cast<const float4*>(&Bs[k][tx*8+4]);
#pragma unroll
            for (int i=0;i<8;i++)
#pragma unroll
                for (int j=0;j<8;j++) acc[i][j] = fmaf(ra[i], rb[j], acc[i][j]);
        }
        __syncthreads();
    }

    float bn[8];
#pragma unroll
    for (int j=0;j<8;j++) bn[j] = bias ? bias[n0 + tx*8 + j] : 0.f;

#pragma unroll
    for (int i=0;i<8;i++) {
        int m = m0 + ty*8 + i;
#pragma unroll
        for (int j4=0;j4<2;j4++) {
            float4 v;
            float* vv = &v.x;
#pragma unroll
            for (int j=0;j<4;j++) {
                float t = acc[i][j4*4+j] + bn[j4*4+j];
                if (EPI == 2) t = 0.5f*t*(1.f + erff(t*0.70710678118654752f));
                vv[j] = t;
            }
            int n = n0 + tx*8 + j4*4;
            if (EPI == 1) {
                int b_ = m >> 12, t_ = m & 4095;     // m = b*T + t, T=4096
                *reinterpret_cast<float4*>(&C[(size_t)t_*(BB*UU) + b_*UU + n]) = v;
            } else if (EPI == 3) {
                float4 r = *reinterpret_cast<const float4*>(&R[(size_t)m*N + n]);
                v.x += r.x; v.y += r.y; v.z += r.z; v.w += r.w;
                *reinterpret_cast<float4*>(&C[(size_t)m*N + n]) = v;
            } else {
                *reinterpret_cast<float4*>(&C[(size_t)m*N + n]) = v;
            }
        }
    }
}

// ---------------- persistent CfC scan (128 CTAs x 384 threads) -------------
// CTA owns 6 u-columns. Warp w: u = w>>1, batches bh..bh+3 (bh = (w&1)*4).
// Full-warp 32-way k-split; lane l owns k = {q*128 + l*4 .. +3}, q<6.
// Inner products via packed fma.rn.f32x2 (FFMA2), h loaded as LDS.128.
__global__ void __launch_bounds__(384, 1) scan_k(
    const float* __restrict__ Wh1, const float* __restrict__ Wh2,
    const float* __restrict__ Wha, const float* __restrict__ Whb,
    const float* __restrict__ x1,  const float* __restrict__ x2,
    const float* __restrict__ xa,  const float* __restrict__ xb)
{
    __shared__ float hs[BB*UU];            // 24KB current h
    __shared__ float4 part[12][4][4];      // [warp][b-local][quarter-partial]
    const int tid  = threadIdx.x;
    const int w    = tid >> 5, lane = tid & 31;
    const int u    = blockIdx.x*6 + (w >> 1);
    const int bh   = (w & 1) * 4;

    // packed weight registers: per gate 12 ulls (q<6, two pairs each)
    ull w1[12], w2[12], wa[12], wb[12];
#pragma unroll
    for (int q=0;q<6;q++) {
#pragma unroll
        for (int hlf=0; hlf<2; hlf++) {
            size_t k = (size_t)(q*128 + lane*4 + hlf*2);
            w1[2*q+hlf] = pk2(Wh1[k*UU + u], Wh1[(k+1)*UU + u]);
            w2[2*q+hlf] = pk2(Wh2[k*UU + u], Wh2[(k+1)*UU + u]);
            wa[2*q+hlf] = pk2(Wha[k*UU + u], Wha[(k+1)*UU + u]);
            wb[2*q+hlf] = pk2(Whb[k*UU + u], Whb[(k+1)*UU + u]);
        }
    }

    // finalize-stage mapping (tid < 48): one (b, u-local) pair each
    const int fu  = tid / 8;
    const int fB  = tid & 7;
    const int fug = blockIdx.x*6 + fu;
    const int fw  = 2*fu + (fB >> 2);
    const int fbl = fB & 3;

    // prefetch xpre for t=0
    float p1=0.f, p2=0.f, pa4=0.f, pb4=0.f;
    if (tid < 48) {
        int xi = fB*UU + fug;
        p1 = x1[xi]; p2 = x2[xi]; pa4 = xa[xi]; pb4 = xb[xi];
    }

    for (int t = 0; t < TT; t++) {
        // stage h into smem
        if (t == 0) {
            for (int p = tid; p < BB*UU; p += 384) hs[p] = 0.f;
        } else {
            const float4* src = reinterpret_cast<const float4*>(g_h[t & 1]);
            float4* dst = reinterpret_cast<float4*>(hs);
#pragma unroll
            for (int p = 0; p < 4; p++) dst[tid + 384*p] = __ldcg(&src[tid + 384*p]);
        }
        __syncthreads();

#pragma unroll
        for (int bl=0; bl<4; bl++) {
            const int b = bh + bl;
            const ulonglong2* hp = reinterpret_cast<const ulonglong2*>(&hs[b*UU]);
            ull a1=0ull, a2=0ull, aa=0ull, ab=0ull;
#pragma unroll
            for (int q=0;q<6;q++) {
                ulonglong2 hv = hp[q*32 + lane];   // LDS.128: pairs (k0,k1),(k2,k3)
                fma2(a1, w1[2*q],   hv.x); fma2(a1, w1[2*q+1], hv.y);
                fma2(a2, w2[2*q],   hv.x); fma2(a2, w2[2*q+1], hv.y);
                fma2(aa, wa[2*q],   hv.x); fma2(aa, wa[2*q+1], hv.y);
                fma2(ab, wb[2*q],   hv.x); fma2(ab, wb[2*q+1], hv.y);
            }
            float lo, hi;
            upk2(lo, hi, a1); float s1 = lo + hi;
            upk2(lo, hi, a2); float s2 = lo + hi;
            upk2(lo, hi, aa); float sa = lo + hi;
            upk2(lo, hi, ab); float sb = lo + hi;
#pragma unroll
            for (int off=16; off>=4; off>>=1) {
                s1 += __shfl_xor_sync(0xffffffffu, s1, off);
                s2 += __shfl_xor_sync(0xffffffffu, s2, off);
                sa += __shfl_xor_sync(0xffffffffu, sa, off);
                sb += __shfl_xor_sync(0xffffffffu, sb, off);
            }
            if (lane < 4) part[w][bl][lane] = make_float4(s1, s2, sa, sb);
        }
        __syncthreads();

        if (tid < 48) {
            float4 q0 = part[fw][fbl][0], q1 = part[fw][fbl][1];
            float4 q2 = part[fw][fbl][2], q3 = part[fw][fbl][3];
            float s1 = (q0.x+q1.x)+(q2.x+q3.x) + p1;
            float s2 = (q0.y+q1.y)+(q2.y+q3.y) + p2;
            float sa = (q0.z+q1.z)+(q2.z+q3.z) + pa4;
            float sb = (q0.w+q1.w)+(q2.w+q3.w) + pb4;
            float f1 = tanhf(s1), f2 = tanhf(s2);
            float ti = 1.f/(1.f + expf(-(sa+sb)));
            float hn = f1 + ti*(f2 - f1);
            __stcg(&g_h[1-(t&1)][fB*UU + fug], hn);
            if (fug < DD) g_cfc[((size_t)fB*TT + t)*DD + fug] = hn;
            // prefetch next step's xpre while others spin at the barrier
            if (t+1 < TT) {
                int xi = (t+1)*(BB*UU) + fB*UU + fug;
                p1 = x1[xi]; p2 = x2[xi]; pa4 = xa[xi]; pb4 = xb[xi];
            }
        }
        __syncthreads();
        if (tid == 0) {        // chip-wide barrier: release-red + acquire-poll
            bar_red_release(&g_bar);
            unsigned target = (unsigned)(t+1)*NSCAN;
            while (ld_acquire(&g_bar) < target) {}
        }
        __syncthreads();
    }
}

// ---------------- LIF gate + residual add ----------------------------------
__global__ void lif_k(const float* __restrict__ thr_p,
                      const float* __restrict__ leak_p,
                      const float* __restrict__ steep_p) {
    int e = blockIdx.x*256 + threadIdx.x;
    int d = e & 511;
    float thr  = fabsf(thr_p[d]) * 0.1f;
    float leak = 1.f/(1.f + expf(-leak_p[d]));
    float sv = steep_p[d];
    float steep = (sv > 20.f) ? sv : log1pf(expf(sv));
    float c = g_cfc[e];
    float fire = 1.f/(1.f + expf(-steep*(fabsf(c) - thr)));
    float gate = fire + leak*(1.f - fire);
    g_x[e] += c*gate;
}

// ---------------- loss: one warp per row of 256 logits ----------------------
__global__ void loss_k(const int* __restrict__ tgt, const float* __restrict__ logits) {
    int row  = blockIdx.x*8 + (threadIdx.x >> 5);
    int lane = threadIdx.x & 31;
    const float* lr = logits + (size_t)row*VV;
    float v[8]; float mx = -3.4e38f;
#pragma unroll
    for (int j=0;j<8;j++) { v[j] = lr[lane + 32*j]; mx = fmaxf(mx, v[j]); }
#pragma unroll
    for (int off=16; off; off>>=1) mx = fmaxf(mx, __shfl_xor_sync(0xffffffffu, mx, off));
    float se = 0.f;
#pragma unroll
    for (int j=0;j<8;j++) se += expf(v[j]-mx);
#pragma unroll
    for (int off=16; off; off>>=1) se += __shfl_xor_sync(0xffffffffu, se, off);
    if (lane == 0) {
        int tv = tgt[row];
        if (tv >= 0) {
            float nll = mx + logf(se) - lr[tv];
            atomicAdd(&g_loss[0], nll);
            atomicAdd(&g_loss[1], 1.f);
        }
    }
}

__global__ void fin_k(float* __restrict__ out, int out_size) {
    if (out_size > MM*VV) out[MM*VV] = g_loss[0]/g_loss[1];
}

__global__ void zero_k() { g_bar = 0u; g_loss[0] = 0.f; g_loss[1] = 0.f; }

// ---------------- driver ----------------------------------------------------
extern "C" void kernel_launch(void* const* d_in, const int* in_sizes, int n_in,
                              void* d_out, int out_size) {
    (void)in_sizes; (void)n_in;
    const int*   idx      = (const int*)  d_in[0];
    const int*   targets  = (const int*)  d_in[1];
    const float* wte      = (const float*)d_in[2];
    const float* ln1_s    = (const float*)d_in[3];
    const float* ln1_b    = (const float*)d_in[4];
    const float* Wff1     = (const float*)d_in[5];
    const float* bff1     = (const float*)d_in[6];
    const float* Wff2     = (const float*)d_in[7];
    const float* bff2     = (const float*)d_in[8];
    const float* Wta      = (const float*)d_in[9];
    const float* bta      = (const float*)d_in[10];
    const float* Wtb      = (const float*)d_in[11];
    const float* btb      = (const float*)d_in[12];
    const float* lif_thr  = (const float*)d_in[13];
    const float* lif_leak = (const float*)d_in[14];
    const float* lif_stp  = (const float*)d_in[15];
    const float* ln2_s    = (const float*)d_in[16];
    const float* ln2_b    = (const float*)d_in[17];
    const float* mW1      = (const float*)d_in[18];
    const float* mb1      = (const float*)d_in[19];
    const float* mW2      = (const float*)d_in[20];
    const float* mb2      = (const float*)d_in[21];
    const float* lnf_s    = (const float*)d_in[22];
    const float* lnf_b    = (const float*)d_in[23];
    float* out = (float*)d_out;

    float *xp, *nm, *mid, *xpre;
    cudaGetSymbolAddress((void**)&xp,   g_x);
    cudaGetSymbolAddress((void**)&nm,   g_nrm);
    cudaGetSymbolAddress((void**)&mid,  g_mid);
    cudaGetSymbolAddress((void**)&xpre, g_xpre);

    embed_k<<<MM*DD/4/256, 256>>>(idx, wte);

    const size_t WSTRIDE = (size_t)(DD+UU)*UU;   // per-layer stride of Wff*/Wt*
    const size_t XG = (size_t)TT*BB*UU;          // per-gate xpre stride

    for (int l = 0; l < LL; l++) {
        ln_k<<<MM,128>>>(xp, ln1_s + l*DD, ln1_b + l*DD, nm);

        const float* Wg[4] = {Wff1, Wff2, Wta, Wtb};
        const float* bg[4] = {bff1, bff2, bta, btb};
        for (int g = 0; g < 4; g++) {
            gemm_k<1,false><<<dim3(UU/128, MM/128), 256>>>(
                nm, Wg[g] + (size_t)l*WSTRIDE, bg[g] + l*UU, nullptr,
                xpre + (size_t)g*XG, MM, UU, DD);
        }

        zero_k<<<1,1>>>();
        scan_k<<<NSCAN, 384>>>(
            Wff1 + (size_t)l*WSTRIDE + (size_t)DD*UU,
            Wff2 + (size_t)l*WSTRIDE + (size_t)DD*UU,
            Wta  + (size_t)l*WSTRIDE + (size_t)DD*UU,
            Wtb  + (size_t)l*WSTRIDE + (size_t)DD*UU,
            xpre, xpre + XG, xpre + 2*XG, xpre + 3*XG);

        lif_k<<<MM*DD/256, 256>>>(lif_thr + l*DD, lif_leak + l*DD, lif_stp + l*DD);

        ln_k<<<MM,128>>>(xp, ln2_s + l*DD, ln2_b + l*DD, nm);
        gemm_k<2,false><<<dim3(DFFC/128, MM/128), 256>>>(
            nm, mW1 + (size_t)l*DD*DFFC, mb1 + l*DFFC, nullptr, mid, MM, DFFC, DD);
        gemm_k<3,false><<<dim3(DD/128, MM/128), 256>>>(
            mid, mW2 + (size_t)l*DFFC*DD, mb2 + l*DD, xp, xp, MM, DD, DFFC);
    }

    ln_k<<<MM,128>>>(xp, lnf_s, lnf_b, nm);
    gemm_k<0,true><<<dim3(VV/128, MM/128), 256>>>(
        nm, wte, nullptr, nullptr, out, MM, VV, DD);
    loss_k<<<MM/8, 256>>>(targets, out);
    fin_k<<<1,1>>>(out, out_size);
}